// round 9
// baseline (speedup 1.0000x reference)
#include <cuda_runtime.h>
#include <cuda_fp16.h>
#include <math_constants.h>
#include <cstdint>

#define BATCH 512
#define SEQ   256
#define EMBD  384
#define HEAD  64
#define NQ    192            // Q|K|V concatenated output columns
#define MROWS (BATCH * SEQ)  // 131072
#define TMQ   128            // CTA M tile
#define TK    32             // K chunk
#define KCH   (EMBD / TK)    // 12

// Scratch (allocation-free rule: device globals)
__device__ __half g_Qh[MROWS * HEAD];   // pre-scaled Q, half
__device__ __half g_Kh[MROWS * HEAD];   // K, half
__device__ __half g_Vh[MROWS * HEAD];   // V, half
__device__ __half g_Wh[NQ * EMBD];      // n-major concat weights [n][k], half
__device__ float  g_bc[NQ];             // concat bias (fp32)

// ---------------------------------------------------------------------------
// helpers
// ---------------------------------------------------------------------------
__device__ __forceinline__ uint32_t packh2(float lo, float hi) {
    __half2 h = __floats2half2_rn(lo, hi);
    return reinterpret_cast<uint32_t&>(h);
}
#define CP_ASYNC16(dst, src) \
    asm volatile("cp.async.cg.shared.global [%0], [%1], 16;" \
                 :: "r"((uint32_t)(dst)), "l"(src) : "memory")
#define CP_COMMIT() asm volatile("cp.async.commit_group;" ::: "memory")
#define CP_WAIT(n)  asm volatile("cp.async.wait_group %0;" :: "n"(n) : "memory")

__device__ __forceinline__ uint32_t smem_u32(const void* p) {
    uint32_t a;
    asm("{ .reg .u64 t; cvta.to.shared.u64 t, %1; cvt.u32.u64 %0, t; }"
        : "=r"(a) : "l"(p));
    return a;
}
__device__ __forceinline__ void ldm_x4(uint32_t* r, uint32_t addr) {
    asm volatile("ldmatrix.sync.aligned.m8n8.x4.shared.b16 {%0,%1,%2,%3}, [%4];"
        : "=r"(r[0]), "=r"(r[1]), "=r"(r[2]), "=r"(r[3]) : "r"(addr));
}
__device__ __forceinline__ void mma_f16(float* d, const uint32_t* a, const uint32_t* b) {
    asm volatile(
        "mma.sync.aligned.m16n8k16.row.col.f32.f16.f16.f32 "
        "{%0,%1,%2,%3}, {%4,%5,%6,%7}, {%8,%9}, {%0,%1,%2,%3};"
        : "+f"(d[0]), "+f"(d[1]), "+f"(d[2]), "+f"(d[3])
        : "r"(a[0]), "r"(a[1]), "r"(a[2]), "r"(a[3]), "r"(b[0]), "r"(b[1]));
}

// ---------------------------------------------------------------------------
// Kernel 0: concat weights to n-major half [n][k], concat bias fp32
// ---------------------------------------------------------------------------
__global__ __launch_bounds__(256) void prep_w(
    const float* __restrict__ Wq, const float* __restrict__ bq,
    const float* __restrict__ Wk, const float* __restrict__ bk,
    const float* __restrict__ Wv, const float* __restrict__ bv)
{
    int idx = blockIdx.x * 256 + threadIdx.x;
    if (idx < NQ * EMBD) {
        int n = idx / EMBD;
        int k = idx - n * EMBD;
        const float* W = (n < 64) ? Wq : (n < 128) ? Wk : Wv;
        g_Wh[idx] = __float2half_rn(W[k * HEAD + (n & 63)]);
    }
    if (idx < NQ) {
        const float* bb = (idx < 64) ? bq : (idx < 128) ? bk : bv;
        g_bc[idx] = bb[idx & 63];
    }
}

// ---------------------------------------------------------------------------
// Kernel 1: QKV projection via mma.sync fp16, all-ldmatrix operand path.
// CTA: [128 x 192] tile, 8 warps (2 M x 4 N), warp tile 64x48.
// A staged as half (LDG->cvt->STS, one-chunk register prefetch);
// B staged via cp.async. Forced 2 CTAs/SM (128-reg cap).
// ---------------------------------------------------------------------------
#define AQ_STRIDE 40                        // half units, row-bank conflict-free
#define BQ_STRIDE 56                        // half units, row-bank conflict-free
#define AS_HALFS (TMQ * AQ_STRIDE)          // 5120 per buffer
#define BS_HALFS (NQ * BQ_STRIDE)           // 10752 per buffer
#define QKV_SMEM_BYTES (2 * (AS_HALFS + BS_HALFS) * 2)   // 63488

__global__ __launch_bounds__(256, 2) void qkv_tc(const float* __restrict__ x)
{
    extern __shared__ __half qsh[];
    __half* As = qsh;                    // 2 x [128][40]
    __half* Bs = qsh + 2 * AS_HALFS;     // 2 x [192][56]

    const int tid  = threadIdx.x;
    const int w    = tid >> 5;
    const int lane = tid & 31;
    const int g    = lane >> 2;     // 0..7
    const int tg   = lane & 3;      // 0..3
    const int lmat = lane >> 3;     // 0..3 (ldmatrix quad)
    const int lr   = lane & 7;
    const int m0   = blockIdx.x * TMQ;
    const int m_w  = (w & 1) * 64;
    const int n_w  = (w >> 1) * 48;

    const uint32_t as_b = smem_u32(As);
    const uint32_t bs_b = smem_u32(Bs);

    // A staging coords: thread -> (row, 16-float half-chunk)
    const int arow = tid >> 1;
    const int acol = (tid & 1) * 16;     // float/half offset within 32-wide chunk

    float acc[4][6][4];
    #pragma unroll
    for (int mb = 0; mb < 4; mb++)
        #pragma unroll
        for (int nb = 0; nb < 6; nb++)
            #pragma unroll
            for (int i = 0; i < 4; i++) acc[mb][nb][i] = 0.0f;

    float4 pf[4];   // A prefetch registers (16 floats)

#define LDG_A(kc) do {                                                          \
        const float4* _p = (const float4*)(x + (size_t)(m0 + arow) * EMBD       \
                                           + (kc) * TK + acol);                 \
        pf[0] = _p[0]; pf[1] = _p[1]; pf[2] = _p[2]; pf[3] = _p[3];             \
    } while (0)

#define STS_A(st) do {                                                          \
        uint4 _h0, _h1;                                                         \
        _h0.x = packh2(pf[0].x, pf[0].y); _h0.y = packh2(pf[0].z, pf[0].w);     \
        _h0.z = packh2(pf[1].x, pf[1].y); _h0.w = packh2(pf[1].z, pf[1].w);     \
        _h1.x = packh2(pf[2].x, pf[2].y); _h1.y = packh2(pf[2].z, pf[2].w);     \
        _h1.z = packh2(pf[3].x, pf[3].y); _h1.w = packh2(pf[3].z, pf[3].w);     \
        uint4* _d = (uint4*)(As + (st) * AS_HALFS + arow * AQ_STRIDE + acol);   \
        _d[0] = _h0; _d[1] = _h1;                                               \
    } while (0)

#define CP_B(kc, st) do {                                                       \
        const int _k0 = (kc) * TK;                                              \
        _Pragma("unroll")                                                       \
        for (int _j = 0; _j < 3; _j++) {                                        \
            int _idx = tid + _j * 256;                                          \
            int _n = _idx >> 2, _c = _idx & 3;                                  \
            uint32_t _bd = bs_b + 2 * ((st) * BS_HALFS + _n * BQ_STRIDE + 8 * _c); \
            CP_ASYNC16(_bd, (const char*)(g_Wh + (size_t)_n * EMBD + _k0 + 8 * _c)); \
        }                                                                       \
    } while (0)

    // ---- prologue ----
    LDG_A(0);
    STS_A(0);
    CP_B(0, 0);
    CP_COMMIT();
    LDG_A(1);

    for (int kc = 0; kc < KCH; kc++) {
        const int st = kc & 1;
        CP_WAIT(0);          // B(kc) arrived
        __syncthreads();     // all warps done with buffer st^1; A(kc) STS visible

        if (kc + 1 < KCH) {  // start B(kc+1) into the other buffer
            CP_B(kc + 1, st ^ 1);
            CP_COMMIT();
        }

        // ---- compute chunk kc from buffer st ----
        const uint32_t ab = as_b + 2 * st * AS_HALFS;
        const uint32_t bb = bs_b + 2 * st * BS_HALFS;
        #pragma unroll
        for (int s = 0; s < 2; s++) {
            const int ks = 16 * s;
            uint32_t bF[3][4];
            #pragma unroll
            for (int p = 0; p < 3; p++) {
                uint32_t addr = bb + 2 * ((n_w + 16 * p + (lmat >> 1) * 8 + lr) * BQ_STRIDE
                                          + ks + (lmat & 1) * 8);
                ldm_x4(bF[p], addr);
            }
            #pragma unroll
            for (int mb = 0; mb < 4; mb++) {
                uint32_t aF[4];
                uint32_t addr = ab + 2 * ((m_w + 16 * mb + (lmat & 1) * 8 + lr) * AQ_STRIDE
                                          + ks + (lmat >> 1) * 8);
                ldm_x4(aF, addr);
                #pragma unroll
                for (int p = 0; p < 3; p++) {
                    mma_f16(acc[mb][2 * p],     aF, bF[p]);
                    mma_f16(acc[mb][2 * p + 1], aF, bF[p] + 2);
                }
            }
        }

        // ---- stage A(kc+1) from regs; prefetch A(kc+2) ----
        if (kc + 1 < KCH) {
            STS_A(st ^ 1);
            if (kc + 2 < KCH) LDG_A(kc + 2);
        }
    }
#undef LDG_A
#undef STS_A
#undef CP_B

    // Epilogue: bias; Q scaled+half, K half, V half
    const float qscale = 0.125f * 1.44269504088896340736f;  // SCALE * log2(e)
    #pragma unroll
    for (int nb = 0; nb < 6; nb++) {
        const int col = n_w + nb * 8 + tg * 2;
        const float2 bbv = *(const float2*)(g_bc + col);
        #pragma unroll
        for (int mb = 0; mb < 4; mb++) {
            #pragma unroll
            for (int h = 0; h < 2; h++) {
                const size_t row = m0 + m_w + mb * 16 + g + h * 8;
                float ox = acc[mb][nb][h * 2 + 0] + bbv.x;
                float oy = acc[mb][nb][h * 2 + 1] + bbv.y;
                if (col < 64) {
                    __half2 v = __floats2half2_rn(ox * qscale, oy * qscale);
                    *(__half2*)(g_Qh + row * HEAD + col) = v;
                } else if (col < 128) {
                    __half2 v = __floats2half2_rn(ox, oy);
                    *(__half2*)(g_Kh + row * HEAD + (col - 64)) = v;
                } else {
                    __half2 v = __floats2half2_rn(ox, oy);
                    *(__half2*)(g_Vh + row * HEAD + (col - 128)) = v;
                }
            }
        }
    }
}

// ---------------------------------------------------------------------------
// Kernel 2: fused causal flash attention, mma.sync fp16, 16 warps / CTA.
// (unchanged from round 8)
// ---------------------------------------------------------------------------
#define SKH   72                 // half units (K rows, P rows)
#define VTS   266                // half units (Vt rows)
#define PQ_OFF   (SEQ * SKH)                   // 18432 halfs
#define VT_OFF   (PQ_OFF + 16 * 16 * SKH)      // 36864 halfs
#define ATT_SMEM_BYTES ((VT_OFF + HEAD * VTS) * 2)   // 107776

__global__ __launch_bounds__(512, 1) void attn_tc(float* __restrict__ out)
{
    extern __shared__ __half sh[];
    __half* Ks = sh;                 // [256][72]
    __half* Ps = sh + PQ_OFF;        // 16 x [16][72] (Q staging, then P bridge)
    __half* Vt = sh + VT_OFF;        // [64][266]

    const int b    = blockIdx.x;
    const int tid  = threadIdx.x;
    const int w    = tid >> 5;
    const int lane = tid & 31;
    const int g    = lane >> 2;
    const int tg   = lane & 3;

    const uint32_t ks_b = smem_u32(Ks);
    const uint32_t ps_b = smem_u32(Ps);

    // ---- stage K (vectorized) and Vt (transposed scalar) ----
    {
        const uint4* Kg = (const uint4*)(g_Kh + (size_t)b * SEQ * HEAD);
        #pragma unroll
        for (int j = 0; j < 4; j++) {
            int idx = tid + j * 512;           // 2048 chunks of 8 halfs
            int row = idx >> 3, c = idx & 7;
            *(uint4*)(Ks + row * SKH + 8 * c) = Kg[idx];
        }
        const uint4* Vg = (const uint4*)(g_Vh + (size_t)b * SEQ * HEAD);
        #pragma unroll
        for (int j = 0; j < 4; j++) {
            int idx = tid + j * 512;
            int s = idx >> 3, c = idx & 7;
            uint4 v = Vg[idx];
            const __half* hv = (const __half*)&v;
            #pragma unroll
            for (int i = 0; i < 8; i++)
                Vt[(8 * c + i) * VTS + s] = hv[i];
        }
    }

    const int qw = (w < 8) ? w : 23 - w;
    __half* Pw = Ps + qw * 16 * SKH;           // warp-private [16][72]
    const uint32_t pw_b = ps_b + qw * 16 * SKH * 2;

    // ---- stage this warp's Q block into its P slice (warp-local) ----
    {
        const uint4* Qg = (const uint4*)(g_Qh + ((size_t)b * SEQ + qw * 16) * HEAD);
        #pragma unroll
        for (int j = 0; j < 4; j++) {
            int idx = lane + j * 32;           // 128 chunks (16 rows x 8)
            int row = idx >> 3, c = idx & 7;
            *(uint4*)(Pw + row * SKH + 8 * c) = Qg[idx];
        }
    }
    __syncwarp();

    // ---- aQ fragments: 4 x ldmatrix.x4 (kt 0..3) ----
    uint32_t aQ[4][4];
    {
        const int mat = lane >> 3, r = lane & 7;
        const int row = (mat & 1) * 8 + r;
        #pragma unroll
        for (int kt = 0; kt < 4; kt++) {
            uint32_t addr = pw_b + 2 * (row * SKH + kt * 16 + (mat >> 1) * 8);
            ldm_x4(aQ[kt], addr);
        }
    }
    __syncthreads();   // K/Vt visible to all; Q fragment loads done before P reuse

    float m_[2] = {-CUDART_INF_F, -CUDART_INF_F};
    float l_[2] = {0.0f, 0.0f};
    float O[8][4];
    #pragma unroll
    for (int nh = 0; nh < 8; nh++)
        #pragma unroll
        for (int e = 0; e < 4; e++) O[nh][e] = 0.0f;

    const int lmat = lane >> 3, lr = lane & 7;

    for (int j = 0; j <= qw; j++) {
        // ---- S = Q @ K_j^T  (16x16) ----
        float sc[2][4] = {{0, 0, 0, 0}, {0, 0, 0, 0}};
        #pragma unroll
        for (int kt = 0; kt < 4; kt++) {
            uint32_t bK[4];
            uint32_t addr = ks_b + 2 * ((16 * j + (lmat >> 1) * 8 + lr) * SKH
                                        + kt * 16 + (lmat & 1) * 8);
            ldm_x4(bK, addr);
            mma_f16(sc[0], aQ[kt], bK);
            mma_f16(sc[1], aQ[kt], bK + 2);
        }

        // ---- causal mask on diagonal block ----
        if (j == qw) {
            #pragma unroll
            for (int nt = 0; nt < 2; nt++)
                #pragma unroll
                for (int hh = 0; hh < 2; hh++)
                    #pragma unroll
                    for (int e = 0; e < 2; e++) {
                        const int rloc = 8 * hh + g;
                        const int cloc = 8 * nt + 2 * tg + e;
                        if (cloc > rloc) sc[nt][2 * hh + e] = -CUDART_INF_F;
                    }
        }

        // ---- online softmax (2 row states) ----
        #pragma unroll
        for (int hh = 0; hh < 2; hh++) {
            float rm = fmaxf(fmaxf(sc[0][2 * hh], sc[0][2 * hh + 1]),
                             fmaxf(sc[1][2 * hh], sc[1][2 * hh + 1]));
            rm = fmaxf(rm, __shfl_xor_sync(0xffffffffu, rm, 1));
            rm = fmaxf(rm, __shfl_xor_sync(0xffffffffu, rm, 2));
            const float nm = fmaxf(m_[hh], rm);
            const float cc = exp2f(m_[hh] - nm);     // 0 on first block
            m_[hh] = nm;
            l_[hh] *= cc;
            #pragma unroll
            for (int nh = 0; nh < 8; nh++) {
                O[nh][2 * hh]     *= cc;
                O[nh][2 * hh + 1] *= cc;
            }
            float rs = 0.0f;
            #pragma unroll
            for (int nt = 0; nt < 2; nt++)
                #pragma unroll
                for (int e = 0; e < 2; e++) {
                    float p = exp2f(sc[nt][2 * hh + e] - nm);
                    rs += p;
                    sc[nt][2 * hh + e] = p;
                }
            rs += __shfl_xor_sync(0xffffffffu, rs, 1);
            rs += __shfl_xor_sync(0xffffffffu, rs, 2);
            l_[hh] += rs;
        }

        // ---- P (half) -> warp-private smem ----
        #pragma unroll
        for (int hh = 0; hh < 2; hh++)
            #pragma unroll
            for (int nt = 0; nt < 2; nt++) {
                uint32_t pp = packh2(sc[nt][2 * hh], sc[nt][2 * hh + 1]);
                *(uint32_t*)(Pw + (8 * hh + g) * SKH + 8 * nt + 2 * tg) = pp;
            }
        __syncwarp();

        // ---- aP fragment (one ldmatrix.x4) ----
        uint32_t aP[4];
        {
            uint32_t addr = pw_b + 2 * (((lmat & 1) * 8 + lr) * SKH + (lmat >> 1) * 8);
            ldm_x4(aP, addr);
        }

        // ---- O += P @ V_j ----
        const int s0 = 16 * j + 2 * tg;
        #pragma unroll
        for (int nh = 0; nh < 8; nh++) {
            uint32_t bV[2];
            const int cv = 8 * nh + g;
            bV[0] = *(const uint32_t*)(Vt + cv * VTS + s0);
            bV[1] = *(const uint32_t*)(Vt + cv * VTS + s0 + 8);
            mma_f16(O[nh], aP, bV);
        }
        __syncwarp();
    }

    // ---- epilogue: normalize + store ----
    #pragma unroll
    for (int hh = 0; hh < 2; hh++) {
        const float inv = 1.0f / l_[hh];
        const size_t row = (size_t)b * SEQ + qw * 16 + 8 * hh + g;
        #pragma unroll
        for (int nh = 0; nh < 8; nh++) {
            float2 o;
            o.x = O[nh][2 * hh]     * inv;
            o.y = O[nh][2 * hh + 1] * inv;
            *(float2*)(out + row * HEAD + 8 * nh + 2 * tg) = o;
        }
    }
}

// ---------------------------------------------------------------------------
extern "C" void kernel_launch(void* const* d_in, const int* in_sizes, int n_in,
                              void* d_out, int out_size)
{
    const float* x  = (const float*)d_in[0];
    const float* Wq = (const float*)d_in[1];
    const float* bq = (const float*)d_in[2];
    const float* Wk = (const float*)d_in[3];
    const float* bk = (const float*)d_in[4];
    const float* Wv = (const float*)d_in[5];
    const float* bv = (const float*)d_in[6];
    float* out = (float*)d_out;

    prep_w<<<(NQ * EMBD + 255) / 256, 256>>>(Wq, bq, Wk, bk, Wv, bv);

    cudaFuncSetAttribute(qkv_tc,
                         cudaFuncAttributeMaxDynamicSharedMemorySize, QKV_SMEM_BYTES);
    qkv_tc<<<MROWS / TMQ, 256, QKV_SMEM_BYTES>>>(x);

    cudaFuncSetAttribute(attn_tc,
                         cudaFuncAttributeMaxDynamicSharedMemorySize, ATT_SMEM_BYTES);
    attn_tc<<<BATCH, 512, ATT_SMEM_BYTES>>>(out);
}

// round 10
// speedup vs baseline: 1.2513x; 1.2513x over previous
#include <cuda_runtime.h>
#include <cuda_fp16.h>
#include <math_constants.h>
#include <cstdint>

#define BATCH 512
#define SEQ   256
#define EMBD  384
#define HEAD  64
#define NQ    192            // Q|K|V concatenated output columns
#define TK    32             // K chunk
#define KCH   (EMBD / TK)    // 12

// Scratch (allocation-free rule: device globals)
__device__ __half g_Wh[NQ * EMBD];      // n-major concat weights [n][k], half
__device__ float  g_bc[NQ];             // concat bias (fp32)

// ---------------------------------------------------------------------------
// helpers
// ---------------------------------------------------------------------------
__device__ __forceinline__ uint32_t packh2(float lo, float hi) {
    __half2 h = __floats2half2_rn(lo, hi);
    return reinterpret_cast<uint32_t&>(h);
}
#define CP_ASYNC16(dst, src) \
    asm volatile("cp.async.cg.shared.global [%0], [%1], 16;" \
                 :: "r"((uint32_t)(dst)), "l"(src) : "memory")
#define CP_COMMIT() asm volatile("cp.async.commit_group;" ::: "memory")
#define CP_WAIT(n)  asm volatile("cp.async.wait_group %0;" :: "n"(n) : "memory")

__device__ __forceinline__ uint32_t smem_u32(const void* p) {
    uint32_t a;
    asm("{ .reg .u64 t; cvta.to.shared.u64 t, %1; cvt.u32.u64 %0, t; }"
        : "=r"(a) : "l"(p));
    return a;
}
__device__ __forceinline__ void ldm_x4(uint32_t* r, uint32_t addr) {
    asm volatile("ldmatrix.sync.aligned.m8n8.x4.shared.b16 {%0,%1,%2,%3}, [%4];"
        : "=r"(r[0]), "=r"(r[1]), "=r"(r[2]), "=r"(r[3]) : "r"(addr));
}
__device__ __forceinline__ void mma_f16(float* d, const uint32_t* a, const uint32_t* b) {
    asm volatile(
        "mma.sync.aligned.m16n8k16.row.col.f32.f16.f16.f32 "
        "{%0,%1,%2,%3}, {%4,%5,%6,%7}, {%8,%9}, {%0,%1,%2,%3};"
        : "+f"(d[0]), "+f"(d[1]), "+f"(d[2]), "+f"(d[3])
        : "r"(a[0]), "r"(a[1]), "r"(a[2]), "r"(a[3]), "r"(b[0]), "r"(b[1]));
}

// ---------------------------------------------------------------------------
// Kernel 0: concat weights to n-major half [n][k], concat bias fp32
// ---------------------------------------------------------------------------
__global__ __launch_bounds__(256) void prep_w(
    const float* __restrict__ Wq, const float* __restrict__ bq,
    const float* __restrict__ Wk, const float* __restrict__ bk,
    const float* __restrict__ Wv, const float* __restrict__ bv)
{
    int idx = blockIdx.x * 256 + threadIdx.x;
    if (idx < NQ * EMBD) {
        int n = idx / EMBD;
        int k = idx - n * EMBD;
        const float* W = (n < 64) ? Wq : (n < 128) ? Wk : Wv;
        g_Wh[idx] = __float2half_rn(W[k * HEAD + (n & 63)]);
    }
    if (idx < NQ) {
        const float* bb = (idx < 64) ? bq : (idx < 128) ? bk : bv;
        g_bc[idx] = bb[idx & 63];
    }
}

// ---------------------------------------------------------------------------
// Fused kernel: one CTA = one batch. 512 threads / 16 warps.
// Phase 1: QKV projection [256 x 192] = x[256 x 384] @ W[384 x 192] (+bias)
//          via mma.sync fp16; Q (scaled, half) / K (half) / V (transposed
//          half) written directly to smem.
// Phase 2: causal flash attention (R8 kernel body) reading that smem.
//
// smem layout (bytes):
//   Ks [256][72]h      @ 0        36864
//   Qs [256][72]h      @ 36864    36864   (16 x [16][72] P slices in phase 2)
//   Vt [64][264]h      @ 73728    33792
//   Ax 2x[256][40]f32  @ 107520   81920   (phase 1 staging)
//   Bw 2x[192][56]h    @ 189440   43008   (phase 1 staging)
//   total                         232448  (= 227 KB exactly)
// ---------------------------------------------------------------------------
#define SKH  72            // half stride, Ks/Qs rows
#define VTS  264           // half stride, Vt rows
#define XS_F (SEQ * 40)    // floats per A buffer (10240)
#define WS_H (NQ * 56)     // halfs per B buffer (10752)
#define FUSED_SMEM 232448

__global__ __launch_bounds__(512) void fused_attn(
    const float* __restrict__ x, float* __restrict__ out)
{
    extern __shared__ char smb[];
    __half* Ks = (__half*)smb;                    // [256][72]
    __half* Qs = (__half*)smb + SEQ * SKH;        // [256][72]
    __half* Vt = (__half*)smb + 2 * SEQ * SKH;    // [64][264]
    float*  Ax = (float*)(smb + 107520);          // 2 x [256][40]
    __half* Bw = (__half*)(smb + 189440);         // 2 x [192][56]

    const int b    = blockIdx.x;
    const int tid  = threadIdx.x;
    const int w    = tid >> 5;
    const int lane = tid & 31;
    const int g    = lane >> 2;
    const int tg   = lane & 3;
    const size_t brow = (size_t)b * SEQ;

    const uint32_t ax_b = smem_u32(Ax);
    const uint32_t bw_b = smem_u32(Bw);
    const uint32_t ks_b = smem_u32(Ks);
    const uint32_t qs_b = smem_u32(Qs);

    // ======================= Phase 1: QKV projection =======================
    {
        const int m_w = (w & 3) * 64;      // 4 M-warps cover 256 rows
        const int n_w = (w >> 2) * 48;     // 4 N-warps cover 192 cols

        float acc[4][6][4];
        #pragma unroll
        for (int mb = 0; mb < 4; mb++)
            #pragma unroll
            for (int nb = 0; nb < 6; nb++)
                #pragma unroll
                for (int i = 0; i < 4; i++) acc[mb][nb][i] = 0.0f;

        // A: 256 rows x 8 16B-chunks = 2048, 4/thread.
        // B: 192 rows x 4 16B-chunks = 768, guarded 2/thread.
#define STAGE(kc, st) do {                                                     \
        const int _k0 = (kc) * TK;                                             \
        _Pragma("unroll")                                                      \
        for (int _j = 0; _j < 4; _j++) {                                       \
            int _idx = tid + _j * 512;                                         \
            int _r = _idx >> 3, _q = _idx & 7;                                 \
            uint32_t _ad = ax_b + 4 * ((st) * XS_F + _r * 40 + 4 * _q);        \
            CP_ASYNC16(_ad, (const char*)(x + (brow + _r) * EMBD + _k0 + 4 * _q)); \
        }                                                                      \
        _Pragma("unroll")                                                      \
        for (int _j = 0; _j < 2; _j++) {                                       \
            int _idx = tid + _j * 512;                                         \
            if (_idx < 768) {                                                  \
                int _n = _idx >> 2, _c = _idx & 3;                             \
                uint32_t _bd = bw_b + 2 * ((st) * WS_H + _n * 56 + 8 * _c);    \
                CP_ASYNC16(_bd, (const char*)(g_Wh + (size_t)_n * EMBD + _k0 + 8 * _c)); \
            }                                                                  \
        }                                                                      \
        CP_COMMIT();                                                           \
    } while (0)

        STAGE(0, 0);

        for (int kc = 0; kc < KCH; kc++) {
            const int st = kc & 1;
            if (kc + 1 < KCH) {
                STAGE(kc + 1, st ^ 1);
                CP_WAIT(1);
            } else {
                CP_WAIT(0);
            }
            __syncthreads();

            const float*  As = Ax + st * XS_F;
            const __half* Bs = Bw + st * WS_H;

            #pragma unroll
            for (int s = 0; s < 2; s++) {
                const int ks = 16 * s;
                // A fragments for all 4 m-tiles (fp32 LDS.64 + pack — R8 path)
                uint32_t AF[4][4];
                #pragma unroll
                for (int mb = 0; mb < 4; mb++) {
                    const int rb = m_w + 16 * mb;
                    float2 p0 = *(const float2*)(As + (rb + g)     * 40 + ks + 2 * tg);
                    float2 p1 = *(const float2*)(As + (rb + g + 8) * 40 + ks + 2 * tg);
                    float2 p2 = *(const float2*)(As + (rb + g)     * 40 + ks + 2 * tg + 8);
                    float2 p3 = *(const float2*)(As + (rb + g + 8) * 40 + ks + 2 * tg + 8);
                    AF[mb][0] = packh2(p0.x, p0.y);
                    AF[mb][1] = packh2(p1.x, p1.y);
                    AF[mb][2] = packh2(p2.x, p2.y);
                    AF[mb][3] = packh2(p3.x, p3.y);
                }
                // B fragments two n-tiles at a time (keeps live regs low)
                #pragma unroll
                for (int p = 0; p < 3; p++) {
                    uint32_t bf[4];
                    const int n0 = n_w + 16 * p + g;
                    bf[0] = *(const uint32_t*)(Bs + n0 * 56 + ks + 2 * tg);
                    bf[1] = *(const uint32_t*)(Bs + n0 * 56 + ks + 2 * tg + 8);
                    bf[2] = *(const uint32_t*)(Bs + (n0 + 8) * 56 + ks + 2 * tg);
                    bf[3] = *(const uint32_t*)(Bs + (n0 + 8) * 56 + ks + 2 * tg + 8);
                    #pragma unroll
                    for (int mb = 0; mb < 4; mb++) {
                        mma_f16(acc[mb][2 * p],     AF[mb], bf);
                        mma_f16(acc[mb][2 * p + 1], AF[mb], bf + 2);
                    }
                }
            }
            __syncthreads();
        }
#undef STAGE

        // Epilogue: bias; Q scaled+half -> Qs, K half -> Ks, V -> Vt (transposed)
        const float qscale = 0.125f * 1.44269504088896340736f;  // SCALE*log2(e)
        #pragma unroll
        for (int nb = 0; nb < 6; nb++) {
            const int col = n_w + nb * 8 + tg * 2;
            const float2 bbv = *(const float2*)(g_bc + col);
            #pragma unroll
            for (int mb = 0; mb < 4; mb++) {
                #pragma unroll
                for (int h = 0; h < 2; h++) {
                    const int row = m_w + mb * 16 + g + h * 8;
                    float ox = acc[mb][nb][h * 2 + 0] + bbv.x;
                    float oy = acc[mb][nb][h * 2 + 1] + bbv.y;
                    if (col < 64) {
                        *(__half2*)(Qs + row * SKH + col) =
                            __floats2half2_rn(ox * qscale, oy * qscale);
                    } else if (col < 128) {
                        *(__half2*)(Ks + row * SKH + (col - 64)) =
                            __floats2half2_rn(ox, oy);
                    } else {
                        Vt[(col - 128) * VTS + row] = __float2half_rn(ox);
                        Vt[(col - 127) * VTS + row] = __float2half_rn(oy);
                    }
                }
            }
        }
    }
    __syncthreads();   // phase boundary: Qs/Ks/Vt complete and visible

    // ======================= Phase 2: flash attention ======================
    const int qw = (w < 8) ? w : 23 - w;   // per-SMSP block counts all = 34
    __half* Pw = Qs + qw * 16 * SKH;       // warp-private [16][72]
    const uint32_t pw_b = qs_b + qw * 16 * SKH * 2;
    const int lmat = lane >> 3, lr = lane & 7;

    // aQ fragments: 4 x ldmatrix.x4 (kt 0..3) from this warp's own Q rows
    uint32_t aQ[4][4];
    {
        const int row = (lmat & 1) * 8 + lr;
        #pragma unroll
        for (int kt = 0; kt < 4; kt++) {
            uint32_t addr = pw_b + 2 * (row * SKH + kt * 16 + (lmat >> 1) * 8);
            ldm_x4(aQ[kt], addr);
        }
    }

    float m_[2] = {-CUDART_INF_F, -CUDART_INF_F};
    float l_[2] = {0.0f, 0.0f};
    float O[8][4];
    #pragma unroll
    for (int nh = 0; nh < 8; nh++)
        #pragma unroll
        for (int e = 0; e < 4; e++) O[nh][e] = 0.0f;

    for (int j = 0; j <= qw; j++) {
        // ---- S = Q @ K_j^T  (16x16) ----
        float sc[2][4] = {{0, 0, 0, 0}, {0, 0, 0, 0}};
        #pragma unroll
        for (int kt = 0; kt < 4; kt++) {
            uint32_t bK[4];
            uint32_t addr = ks_b + 2 * ((16 * j + (lmat >> 1) * 8 + lr) * SKH
                                        + kt * 16 + (lmat & 1) * 8);
            ldm_x4(bK, addr);
            mma_f16(sc[0], aQ[kt], bK);
            mma_f16(sc[1], aQ[kt], bK + 2);
        }

        // ---- causal mask on diagonal block ----
        if (j == qw) {
            #pragma unroll
            for (int nt = 0; nt < 2; nt++)
                #pragma unroll
                for (int hh = 0; hh < 2; hh++)
                    #pragma unroll
                    for (int e = 0; e < 2; e++) {
                        const int rloc = 8 * hh + g;
                        const int cloc = 8 * nt + 2 * tg + e;
                        if (cloc > rloc) sc[nt][2 * hh + e] = -CUDART_INF_F;
                    }
        }

        // ---- online softmax (2 row states) ----
        #pragma unroll
        for (int hh = 0; hh < 2; hh++) {
            float rm = fmaxf(fmaxf(sc[0][2 * hh], sc[0][2 * hh + 1]),
                             fmaxf(sc[1][2 * hh], sc[1][2 * hh + 1]));
            rm = fmaxf(rm, __shfl_xor_sync(0xffffffffu, rm, 1));
            rm = fmaxf(rm, __shfl_xor_sync(0xffffffffu, rm, 2));
            const float nm = fmaxf(m_[hh], rm);
            const float cc = exp2f(m_[hh] - nm);     // 0 on first block
            m_[hh] = nm;
            l_[hh] *= cc;
            #pragma unroll
            for (int nh = 0; nh < 8; nh++) {
                O[nh][2 * hh]     *= cc;
                O[nh][2 * hh + 1] *= cc;
            }
            float rs = 0.0f;
            #pragma unroll
            for (int nt = 0; nt < 2; nt++)
                #pragma unroll
                for (int e = 0; e < 2; e++) {
                    float p = exp2f(sc[nt][2 * hh + e] - nm);
                    rs += p;
                    sc[nt][2 * hh + e] = p;
                }
            rs += __shfl_xor_sync(0xffffffffu, rs, 1);
            rs += __shfl_xor_sync(0xffffffffu, rs, 2);
            l_[hh] += rs;
        }

        // ---- P (half) -> warp-private smem ----
        #pragma unroll
        for (int hh = 0; hh < 2; hh++)
            #pragma unroll
            for (int nt = 0; nt < 2; nt++) {
                uint32_t pp = packh2(sc[nt][2 * hh], sc[nt][2 * hh + 1]);
                *(uint32_t*)(Pw + (8 * hh + g) * SKH + 8 * nt + 2 * tg) = pp;
            }
        __syncwarp();

        // ---- aP fragment (one ldmatrix.x4) ----
        uint32_t aP[4];
        {
            uint32_t addr = pw_b + 2 * (((lmat & 1) * 8 + lr) * SKH + (lmat >> 1) * 8);
            ldm_x4(aP, addr);
        }

        // ---- O += P @ V_j ----
        const int s0 = 16 * j + 2 * tg;
        #pragma unroll
        for (int nh = 0; nh < 8; nh++) {
            uint32_t bV[2];
            const int cv = 8 * nh + g;
            bV[0] = *(const uint32_t*)(Vt + cv * VTS + s0);
            bV[1] = *(const uint32_t*)(Vt + cv * VTS + s0 + 8);
            mma_f16(O[nh], aP, bV);
        }
        __syncwarp();
    }

    // ---- epilogue: normalize + store ----
    #pragma unroll
    for (int hh = 0; hh < 2; hh++) {
        const float inv = 1.0f / l_[hh];
        const size_t row = brow + qw * 16 + 8 * hh + g;
        #pragma unroll
        for (int nh = 0; nh < 8; nh++) {
            float2 o;
            o.x = O[nh][2 * hh]     * inv;
            o.y = O[nh][2 * hh + 1] * inv;
            *(float2*)(out + row * HEAD + 8 * nh + 2 * tg) = o;
        }
    }
}

// ---------------------------------------------------------------------------
extern "C" void kernel_launch(void* const* d_in, const int* in_sizes, int n_in,
                              void* d_out, int out_size)
{
    const float* x  = (const float*)d_in[0];
    const float* Wq = (const float*)d_in[1];
    const float* bq = (const float*)d_in[2];
    const float* Wk = (const float*)d_in[3];
    const float* bk = (const float*)d_in[4];
    const float* Wv = (const float*)d_in[5];
    const float* bv = (const float*)d_in[6];
    float* out = (float*)d_out;

    prep_w<<<(NQ * EMBD + 255) / 256, 256>>>(Wq, bq, Wk, bk, Wv, bv);

    cudaFuncSetAttribute(fused_attn,
                         cudaFuncAttributeMaxDynamicSharedMemorySize, FUSED_SMEM);
    fused_attn<<<BATCH, 512, FUSED_SMEM>>>(x, out);
}